// round 1
// baseline (speedup 1.0000x reference)
#include <cuda_runtime.h>

// Problem constants
#define B_   2
#define T_   2048
#define C_   1024
#define H_   16
#define HD_  64
#define M_   (B_*T_)    // 4096
#define BH_  (B_*H_)    // 32
#define SM_SCALE 0.125f // 1/sqrt(64)

// Scratch (device globals: allocation-guard safe)
__device__ float g_q[(size_t)BH_*T_*HD_];
__device__ float g_k[(size_t)BH_*T_*HD_];
__device__ float g_v[(size_t)BH_*T_*HD_];
__device__ float g_y[(size_t)M_*C_];

// ---------------------------------------------------------------------------
// SGEMM: Out[m,n] = sum_k A[m,k]*W[k,n] + bias[n]
// BM=BN=128, BK=8, 256 threads, 8x8 per thread.
// split==1: store into head-split layout [b*H+h][t][hd] (m=b*T+t, n=h*HD+hd)
// ---------------------------------------------------------------------------
__global__ __launch_bounds__(256, 2)
void sgemm_kernel(const float* __restrict__ A, const float* __restrict__ W,
                  const float* __restrict__ bias, float* __restrict__ Out,
                  int M, int N, int K, int split)
{
    __shared__ float As[8][128];
    __shared__ float Bs[8][128];

    const int tid  = threadIdx.x;
    const int brow = blockIdx.y * 128;
    const int bcol = blockIdx.x * 128;

    const int arow = tid >> 1;          // 0..127
    const int acol = (tid & 1) << 2;    // 0 or 4
    const int wrow = tid >> 5;          // 0..7
    const int wcol = (tid & 31) << 2;   // 0..124

    const float* Ap = A + (size_t)(brow + arow) * K + acol;
    const float* Bp = W + (size_t)wrow * N + bcol + wcol;

    const int trow = (tid >> 4) << 3;   // 0..120
    const int tcol = (tid & 15) << 3;   // 0..120

    float acc[8][8];
    #pragma unroll
    for (int i = 0; i < 8; i++)
        #pragma unroll
        for (int j = 0; j < 8; j++) acc[i][j] = 0.f;

    for (int k0 = 0; k0 < K; k0 += 8) {
        float4 av = *(const float4*)(Ap + k0);
        As[acol + 0][arow] = av.x;
        As[acol + 1][arow] = av.y;
        As[acol + 2][arow] = av.z;
        As[acol + 3][arow] = av.w;
        *(float4*)&Bs[wrow][wcol] = *(const float4*)(Bp + (size_t)k0 * N);
        __syncthreads();

        #pragma unroll
        for (int k = 0; k < 8; k++) {
            float a[8], b[8];
            *(float4*)&a[0] = *(const float4*)&As[k][trow];
            *(float4*)&a[4] = *(const float4*)&As[k][trow + 4];
            *(float4*)&b[0] = *(const float4*)&Bs[k][tcol];
            *(float4*)&b[4] = *(const float4*)&Bs[k][tcol + 4];
            #pragma unroll
            for (int i = 0; i < 8; i++)
                #pragma unroll
                for (int j = 0; j < 8; j++)
                    acc[i][j] = fmaf(a[i], b[j], acc[i][j]);
        }
        __syncthreads();
    }

    float bv[8];
    #pragma unroll
    for (int j = 0; j < 8; j++) bv[j] = bias[bcol + tcol + j];

    if (!split) {
        #pragma unroll
        for (int i = 0; i < 8; i++) {
            float* dst = Out + (size_t)(brow + trow + i) * N + bcol + tcol;
            float4 v0 = make_float4(acc[i][0]+bv[0], acc[i][1]+bv[1],
                                    acc[i][2]+bv[2], acc[i][3]+bv[3]);
            float4 v1 = make_float4(acc[i][4]+bv[4], acc[i][5]+bv[5],
                                    acc[i][6]+bv[6], acc[i][7]+bv[7]);
            *(float4*)(dst)     = v0;
            *(float4*)(dst + 4) = v1;
        }
    } else {
        // n = h*64 + hd ; tcol multiple of 8 so all 8 cols share one head
        const int n  = bcol + tcol;
        const int h  = n >> 6;
        const int hd = n & 63;
        #pragma unroll
        for (int i = 0; i < 8; i++) {
            const int m  = brow + trow + i;     // m = b*T + t
            const int bb = m >> 11;             // /2048
            const int t  = m & 2047;
            float* dst = Out + (((size_t)(bb*H_ + h) * T_) + t) * HD_ + hd;
            float4 v0 = make_float4(acc[i][0]+bv[0], acc[i][1]+bv[1],
                                    acc[i][2]+bv[2], acc[i][3]+bv[3]);
            float4 v1 = make_float4(acc[i][4]+bv[4], acc[i][5]+bv[5],
                                    acc[i][6]+bv[6], acc[i][7]+bv[7]);
            *(float4*)(dst)     = v0;
            *(float4*)(dst + 4) = v1;
        }
    }
}

// ---------------------------------------------------------------------------
// Flash attention, fp32. 64x64 tiles, online softmax, causal tile skipping.
// grid = (T/64, B*H), 256 threads (16x16, 4x4 micro-tiles).
// Q/K stored transposed (d-major) in smem for conflict-free float4 reads.
// ---------------------------------------------------------------------------
#define LDP 68  // smem row pitch (floats), multiple of 4 for float4 alignment
#define ATTN_SMEM (4 * 64 * LDP * 4)

__device__ __forceinline__ void load_tile_T(const float* __restrict__ src,
                                            float* dst, int tid, float scale)
{
    // src: [64][64] row-major (row=pos, col=d) -> dst[d*LDP + pos], scaled
    const int r  = tid >> 2;
    const int d0 = (tid & 3) << 4;
    #pragma unroll
    for (int i = 0; i < 4; i++) {
        float4 v = *(const float4*)(src + (size_t)r * HD_ + d0 + i * 4);
        const int d = d0 + i * 4;
        dst[(d + 0) * LDP + r] = v.x * scale;
        dst[(d + 1) * LDP + r] = v.y * scale;
        dst[(d + 2) * LDP + r] = v.z * scale;
        dst[(d + 3) * LDP + r] = v.w * scale;
    }
}

__device__ __forceinline__ void load_tile(const float* __restrict__ src,
                                          float* dst, int tid)
{
    const int r  = tid >> 2;
    const int d0 = (tid & 3) << 4;
    #pragma unroll
    for (int i = 0; i < 4; i++)
        *(float4*)(dst + (size_t)r * LDP + d0 + i * 4) =
            *(const float4*)(src + (size_t)r * HD_ + d0 + i * 4);
}

__global__ __launch_bounds__(256)
void attn_kernel(const float* __restrict__ Qg, const float* __restrict__ Kg,
                 const float* __restrict__ Vg, float* __restrict__ Yg)
{
    extern __shared__ float smem[];
    float* QsT = smem;                 // [64][LDP] d-major
    float* KsT = QsT + 64 * LDP;       // [64][LDP] d-major
    float* Vs  = KsT + 64 * LDP;       // [64][LDP] k-major (row=k pos, col=d)
    float* Ps  = Vs  + 64 * LDP;       // [64][LDP] k-major (row=k pos, col=q row)

    const int tid = threadIdx.x;
    const int qt  = blockIdx.x;
    const int bh  = blockIdx.y;
    const int ty4 = (tid >> 4) << 2;   // q-row base (0..60)
    const int tx4 = (tid & 15) << 2;   // col base   (0..60)

    const float* Qb = Qg + (size_t)bh * T_ * HD_;
    const float* Kb = Kg + (size_t)bh * T_ * HD_;
    const float* Vb = Vg + (size_t)bh * T_ * HD_;

    load_tile_T(Qb + (size_t)qt * 64 * HD_, QsT, tid, SM_SCALE);

    float m_i[4], l_i[4], o[4][4];
    #pragma unroll
    for (int i = 0; i < 4; i++) {
        m_i[i] = -1e30f; l_i[i] = 0.f;
        #pragma unroll
        for (int j = 0; j < 4; j++) o[i][j] = 0.f;
    }

    for (int kt = 0; kt <= qt; kt++) {
        __syncthreads();  // previous P@V reads done before overwrite
        load_tile_T(Kb + (size_t)kt * 64 * HD_, KsT, tid, 1.0f);
        load_tile  (Vb + (size_t)kt * 64 * HD_, Vs, tid);
        __syncthreads();

        // S = Q K^T (Q pre-scaled)
        float s[4][4];
        #pragma unroll
        for (int i = 0; i < 4; i++)
            #pragma unroll
            for (int j = 0; j < 4; j++) s[i][j] = 0.f;

        #pragma unroll 8
        for (int d = 0; d < 64; d++) {
            float a[4], b[4];
            *(float4*)a = *(const float4*)&QsT[d * LDP + ty4];
            *(float4*)b = *(const float4*)&KsT[d * LDP + tx4];
            #pragma unroll
            for (int i = 0; i < 4; i++)
                #pragma unroll
                for (int j = 0; j < 4; j++)
                    s[i][j] = fmaf(a[i], b[j], s[i][j]);
        }

        if (kt == qt) {   // diagonal tile: causal mask within tile
            #pragma unroll
            for (int i = 0; i < 4; i++)
                #pragma unroll
                for (int j = 0; j < 4; j++)
                    if (tx4 + j > ty4 + i) s[i][j] = -1e30f;
        }

        // online softmax (rows split across 16 lanes; shuffle over tx)
        #pragma unroll
        for (int i = 0; i < 4; i++) {
            float mx = fmaxf(fmaxf(s[i][0], s[i][1]), fmaxf(s[i][2], s[i][3]));
            #pragma unroll
            for (int off = 8; off; off >>= 1)
                mx = fmaxf(mx, __shfl_xor_sync(0xffffffffu, mx, off));
            const float mn   = fmaxf(m_i[i], mx);
            const float corr = __expf(m_i[i] - mn);
            m_i[i] = mn;
            float ps = 0.f;
            #pragma unroll
            for (int j = 0; j < 4; j++) {
                s[i][j] = __expf(s[i][j] - mn);
                ps += s[i][j];
            }
            #pragma unroll
            for (int off = 8; off; off >>= 1)
                ps += __shfl_xor_sync(0xffffffffu, ps, off);
            l_i[i] = l_i[i] * corr + ps;
            #pragma unroll
            for (int j = 0; j < 4; j++) o[i][j] *= corr;
        }

        // write P transposed (k-major) for the second GEMM
        #pragma unroll
        for (int j = 0; j < 4; j++) {
            float4 pv = make_float4(s[0][j], s[1][j], s[2][j], s[3][j]);
            *(float4*)&Ps[(tx4 + j) * LDP + ty4] = pv;
        }
        __syncthreads();

        // O += P @ V
        #pragma unroll 8
        for (int k = 0; k < 64; k++) {
            float a[4], b[4];
            *(float4*)a = *(const float4*)&Ps[k * LDP + ty4];
            *(float4*)b = *(const float4*)&Vs[k * LDP + tx4];
            #pragma unroll
            for (int i = 0; i < 4; i++)
                #pragma unroll
                for (int j = 0; j < 4; j++)
                    o[i][j] = fmaf(a[i], b[j], o[i][j]);
        }
    }

    // epilogue: normalize, write y in [B,T,C] layout
    const int bb = bh >> 4;
    const int h  = bh & 15;
    #pragma unroll
    for (int i = 0; i < 4; i++) {
        const float inv = 1.0f / l_i[i];
        const int t = qt * 64 + ty4 + i;
        float4 yv = make_float4(o[i][0]*inv, o[i][1]*inv, o[i][2]*inv, o[i][3]*inv);
        *(float4*)(Yg + ((size_t)(bb * T_ + t)) * C_ + h * HD_ + tx4) = yv;
    }
}

// ---------------------------------------------------------------------------
extern "C" void kernel_launch(void* const* d_in, const int* in_sizes, int n_in,
                              void* d_out, int out_size)
{
    const float* query = (const float*)d_in[0];
    const float* key   = (const float*)d_in[1];
    const float* value = (const float*)d_in[2];
    // d_in[3] = att_mask (causal tril; provably unused)
    const float* Wq = (const float*)d_in[4];
    const float* bq = (const float*)d_in[5];
    const float* Wk = (const float*)d_in[6];
    const float* bk = (const float*)d_in[7];
    const float* Wv = (const float*)d_in[8];
    const float* bv = (const float*)d_in[9];
    const float* Wp = (const float*)d_in[10];
    const float* bp = (const float*)d_in[11];
    float* out = (float*)d_out;

    float *gq, *gk, *gv, *gy;
    cudaGetSymbolAddress((void**)&gq, g_q);
    cudaGetSymbolAddress((void**)&gk, g_k);
    cudaGetSymbolAddress((void**)&gv, g_v);
    cudaGetSymbolAddress((void**)&gy, g_y);

    cudaFuncSetAttribute(attn_kernel,
                         cudaFuncAttributeMaxDynamicSharedMemorySize, ATTN_SMEM);

    dim3 ggrid(C_ / 128, M_ / 128);  // (8, 32)
    sgemm_kernel<<<ggrid, 256>>>(query, Wq, bq, gq, M_, C_, C_, 1);
    sgemm_kernel<<<ggrid, 256>>>(key,   Wk, bk, gk, M_, C_, C_, 1);
    sgemm_kernel<<<ggrid, 256>>>(value, Wv, bv, gv, M_, C_, C_, 1);

    attn_kernel<<<dim3(T_ / 64, BH_), 256, ATTN_SMEM>>>(gq, gk, gv, gy);

    sgemm_kernel<<<ggrid, 256>>>(gy, Wp, bp, out, M_, C_, C_, 0);
}